// round 15
// baseline (speedup 1.0000x reference)
#include <cuda_runtime.h>
#include <math_constants.h>

// ChamferLoss single-kernel fused-direction (R7/R14 engine, 93% of fma-port
// floor) with IN-KERNEL final reduction: last-arriving block per partial group
// reduces it (L2-hot, overlapped with other blocks' compute); globally-last
// unit writes out[0] and resets state for graph-replay determinism.
// d2 = -2 x.y + (|x|^2 + |y|^2): 4 fma-pipe ops/pair + 2 FMNMX (alu).

#define B_DIM  8
#define N_PTS  4096
#define TPB    256
#define NWARP  8
#define PTS    16                 // queries per thread
#define QPB    512                // queries per block (32 lanes * PTS)
#define NQB    (N_PTS / QPB)      // 8 query blocks
#define CSPLIT 4
#define CPB    (N_PTS / CSPLIT)   // 1024 candidates per block
#define CPW    (CPB / NWARP)      // 128 candidates per warp
#define NQUAD  (CPW / 4)          // 32 quads per warp
#define NUNITS (B_DIM * NQB + B_DIM * CSPLIT)   // 96 reduction units
#define EPS    1e-8f

__device__ float g_xpart[B_DIM][N_PTS][CSPLIT];  // [b][q][z]  (16B rows)
__device__ float g_ypart[B_DIM][N_PTS][NQB];     // [b][c][qb] (32B rows)
__device__ int   g_xcnt[B_DIM][NQB];
__device__ int   g_ycnt[B_DIM][CSPLIT];
__device__ int   g_fin;
__device__ float g_acc;

__global__ __launch_bounds__(TPB, 2) void chamfer_main(
    const float* __restrict__ x1, const float* __restrict__ y1,
    float* __restrict__ out, float scale)
{
    __shared__ float4 sC[CPB];            // (-2rx,-2ry,-2rz,rsq): 16KB
    __shared__ float  sY[CPB];            // ymin partials (warp-exclusive ranges)
    __shared__ float  sPart[NWARP][QPB];  // xmin partials: 16KB
    __shared__ int    sLastX, sLastY;
    __shared__ float  wsum[NWARP];

    const int b     = blockIdx.y;
    const int qb    = blockIdx.x;
    const int z     = blockIdx.z;
    const int qbase = qb * QPB;
    const int cbase = z * CPB;
    const float* Qb = x1 + (size_t)b * N_PTS * 3;
    const float* Rb = y1 + (size_t)b * N_PTS * 3;

    const int tid = threadIdx.x;
    const int u   = tid & 31;
    const int w   = tid >> 5;

    // tile fill: candidate record = (-2rx, -2ry, -2rz, rsq)
    for (int i = tid; i < CPB; i += TPB) {
        const float* r = Rb + (size_t)(cbase + i) * 3;
        const float rx = r[0], ry = r[1], rz = r[2];
        sC[i] = make_float4(-2.0f * rx, -2.0f * ry, -2.0f * rz,
                            fmaf(rx, rx, fmaf(ry, ry, rz * rz)));
        sY[i] = CUDART_INF_F;
    }

    // 16 queries per thread
    float qx[PTS], qy[PTS], qz[PTS], xsq[PTS], mn[PTS];
    #pragma unroll
    for (int k = 0; k < PTS; ++k) {
        const int p = qbase + u + k * 32;
        qx[k] = Qb[p * 3 + 0];
        qy[k] = Qb[p * 3 + 1];
        qz[k] = Qb[p * 3 + 2];
        xsq[k] = fmaf(qx[k], qx[k], fmaf(qy[k], qy[k], qz[k] * qz[k]));
        mn[k] = CUDART_INF_F;
    }
    __syncthreads();

    // rotating quad ownership: at step s, lane u owns quad (u+s)&31 of warp w's
    // 128-candidate slice. Converged warp => sequential steps => race-free sY rmw.
    const int wslice = w * CPW;
    for (int s = 0; s < NQUAD; ++s) {
        const int qd   = (u + s) & (NQUAD - 1);
        const int cidx = wslice + qd * 4;

        float4 C[4];
        #pragma unroll
        for (int c = 0; c < 4; ++c) C[c] = sC[cidx + c];

        float my[4];
        #pragma unroll
        for (int c = 0; c < 4; ++c) my[c] = sY[cidx + c];

        #pragma unroll
        for (int c = 0; c < 4; ++c) {
            const float c0 = C[c].x, c1 = C[c].y, c2 = C[c].z, rsq = C[c].w;
            float ml = my[c];
            #pragma unroll
            for (int k = 0; k < PTS; ++k) {
                const float S = xsq[k] + rsq;        // 1 FADD
                float t = fmaf(c2, qz[k], S);        // 3 FFMA
                t = fmaf(c1, qy[k], t);
                t = fmaf(c0, qx[k], t);
                mn[k] = fminf(mn[k], t);             // 2 FMNMX (alu)
                ml    = fminf(ml, t);
            }
            my[c] = ml;
        }

        #pragma unroll
        for (int c = 0; c < 4; ++c) sY[cidx + c] = my[c];
    }

    // publish xmin partials
    #pragma unroll
    for (int k = 0; k < PTS; ++k) sPart[w][u + k * 32] = mn[k];
    __syncthreads();

    // combine xmin across warps -> exclusive transposed slot
    for (int q = tid; q < QPB; q += TPB) {
        float m = sPart[0][q];
        #pragma unroll
        for (int ww = 1; ww < NWARP; ++ww) m = fminf(m, sPart[ww][q]);
        g_xpart[b][qbase + q][z] = m;
    }
    // ymin -> exclusive transposed slot
    for (int i = tid; i < CPB; i += TPB)
        g_ypart[b][cbase + i][qb] = sY[i];

    // ---- in-kernel reduction: last arriver of each group reduces it ----
    __threadfence();
    if (tid == 0) {
        sLastX = (atomicAdd(&g_xcnt[b][qb], 1) == CSPLIT - 1);
        sLastY = (atomicAdd(&g_ycnt[b][z],  1) == NQB - 1);
    }
    __syncthreads();

    const int lastX = sLastX;
    const int lastY = sLastY;
    if (!lastX && !lastY) return;

    float local = 0.0f;
    if (lastX) {   // reduce x-side for (b, qb): QPB queries x CSPLIT floats
        for (int q = tid; q < QPB; q += TPB) {
            const float4 p = *reinterpret_cast<const float4*>(&g_xpart[b][qbase + q][0]);
            const float m = fminf(fminf(p.x, p.y), fminf(p.z, p.w));
            local += sqrtf(fmaxf(m, 0.0f) + EPS);
        }
    }
    if (lastY) {   // reduce y-side for (b, z): CPB candidates x NQB floats
        for (int i = tid; i < CPB; i += TPB) {
            const float4 p0 = *reinterpret_cast<const float4*>(&g_ypart[b][cbase + i][0]);
            const float4 p1 = *reinterpret_cast<const float4*>(&g_ypart[b][cbase + i][4]);
            const float m0 = fminf(fminf(p0.x, p0.y), fminf(p0.z, p0.w));
            const float m1 = fminf(fminf(p1.x, p1.y), fminf(p1.z, p1.w));
            local += sqrtf(fmaxf(fminf(m0, m1), 0.0f) + EPS);
        }
    }

    // block-sum local
    #pragma unroll
    for (int off = 16; off > 0; off >>= 1)
        local += __shfl_xor_sync(0xFFFFFFFFu, local, off);
    if (u == 0) wsum[w] = local;
    __syncthreads();

    if (tid == 0) {
        float total = 0.0f;
        #pragma unroll
        for (int ww = 0; ww < NWARP; ++ww) total += wsum[ww];

        // reset group counters (we are the unique last arriver) BEFORE g_fin
        if (lastX) g_xcnt[b][qb] = 0;
        if (lastY) g_ycnt[b][z]  = 0;

        atomicAdd(&g_acc, total);
        __threadfence();

        const int units = lastX + lastY;
        const int old = atomicAdd(&g_fin, units);
        if (old + units == NUNITS) {
            __threadfence();
            const float acc = atomicAdd(&g_acc, 0.0f);   // serialized L2 read
            out[0] = acc * scale;
            g_acc = 0.0f;    // reset for next graph replay
            g_fin = 0;
        }
    }
}

extern "C" void kernel_launch(void* const* d_in, const int* in_sizes, int n_in,
                              void* d_out, int out_size)
{
    const float* x1 = (const float*)d_in[0];
    const float* y1 = (const float*)d_in[1];
    float* out = (float*)d_out;

    dim3 grid(NQB, B_DIM, CSPLIT);   // (8, 8, 4) = 256 blocks x 8 warps
    const float scale = 1.0f / (float)(B_DIM * N_PTS);
    chamfer_main<<<grid, TPB>>>(x1, y1, out, scale);
}

// round 16
// speedup vs baseline: 1.0621x; 1.0621x over previous
#include <cuda_runtime.h>
#include <math_constants.h>

// ChamferLoss fused-direction kernel (R7/R14 engine, ~93% of fma-port floor)
// + MLP-batched pass2: each reducer thread issues 8 INDEPENDENT float4 loads
// (x-side: 8 consecutive queries; y-side: 4 candidates x 2) so DRAM/L2 latency
// is overlapped (MLP=8) instead of exposed serially.
// d2 = -2 x.y + (|x|^2 + |y|^2): 4 fma-pipe ops/pair + 2 FMNMX (alu).

#define B_DIM  8
#define N_PTS  4096
#define TPB    256
#define NWARP  8
#define PTS    16                 // queries per thread
#define QPB    512                // queries per block (32 lanes * PTS)
#define NQB    (N_PTS / QPB)      // 8 query blocks
#define CSPLIT 4
#define CPB    (N_PTS / CSPLIT)   // 1024 candidates per block
#define CPW    (CPB / NWARP)      // 128 candidates per warp
#define NQUAD  (CPW / 4)          // 32 quads per warp
#define EPS    1e-8f

// pass2 geometry: x-side 32768 entries / 8 per thread = 4096 threads (16 blocks)
//                 y-side 32768 entries / 4 per thread = 8192 threads (32 blocks)
#define P2_XBLK 16
#define P2_YBLK 32
#define P2_BLK  (P2_XBLK + P2_YBLK)

__device__ float g_xpart[B_DIM][N_PTS][CSPLIT];  // [b][q][z]  (16B rows)
__device__ float g_ypart[B_DIM][N_PTS][NQB];     // [b][c][qb] (32B rows)

__global__ __launch_bounds__(TPB, 2) void chamfer_main(
    const float* __restrict__ x1, const float* __restrict__ y1,
    float* __restrict__ out)
{
    __shared__ float4 sC[CPB];            // (-2rx,-2ry,-2rz,rsq): 16KB
    __shared__ float  sY[CPB];            // ymin partials (warp-exclusive ranges)
    __shared__ float  sPart[NWARP][QPB];  // xmin partials: 16KB

    const int b     = blockIdx.y;
    const int qb    = blockIdx.x;
    const int qbase = qb * QPB;
    const int cbase = blockIdx.z * CPB;
    const float* Qb = x1 + (size_t)b * N_PTS * 3;
    const float* Rb = y1 + (size_t)b * N_PTS * 3;

    const int tid = threadIdx.x;
    const int u   = tid & 31;
    const int w   = tid >> 5;

    if (qb == 0 && b == 0 && blockIdx.z == 0 && tid == 0) out[0] = 0.0f;

    // tile fill: candidate record = (-2rx, -2ry, -2rz, rsq)
    for (int i = tid; i < CPB; i += TPB) {
        const float* r = Rb + (size_t)(cbase + i) * 3;
        const float rx = r[0], ry = r[1], rz = r[2];
        sC[i] = make_float4(-2.0f * rx, -2.0f * ry, -2.0f * rz,
                            fmaf(rx, rx, fmaf(ry, ry, rz * rz)));
        sY[i] = CUDART_INF_F;
    }

    // 16 queries per thread
    float qx[PTS], qy[PTS], qz[PTS], xsq[PTS], mn[PTS];
    #pragma unroll
    for (int k = 0; k < PTS; ++k) {
        const int p = qbase + u + k * 32;
        qx[k] = Qb[p * 3 + 0];
        qy[k] = Qb[p * 3 + 1];
        qz[k] = Qb[p * 3 + 2];
        xsq[k] = fmaf(qx[k], qx[k], fmaf(qy[k], qy[k], qz[k] * qz[k]));
        mn[k] = CUDART_INF_F;
    }
    __syncthreads();

    // rotating quad ownership: at step s, lane u owns quad (u+s)&31 of warp w's
    // 128-candidate slice. Converged warp => sequential steps => race-free sY rmw.
    const int wslice = w * CPW;
    for (int s = 0; s < NQUAD; ++s) {
        const int qd   = (u + s) & (NQUAD - 1);
        const int cidx = wslice + qd * 4;

        float4 C[4];
        #pragma unroll
        for (int c = 0; c < 4; ++c) C[c] = sC[cidx + c];

        float my[4];
        #pragma unroll
        for (int c = 0; c < 4; ++c) my[c] = sY[cidx + c];

        #pragma unroll
        for (int c = 0; c < 4; ++c) {
            const float c0 = C[c].x, c1 = C[c].y, c2 = C[c].z, rsq = C[c].w;
            float ml = my[c];
            #pragma unroll
            for (int k = 0; k < PTS; ++k) {
                const float S = xsq[k] + rsq;        // 1 FADD
                float t = fmaf(c2, qz[k], S);        // 3 FFMA
                t = fmaf(c1, qy[k], t);
                t = fmaf(c0, qx[k], t);
                mn[k] = fminf(mn[k], t);             // 2 FMNMX (alu)
                ml    = fminf(ml, t);
            }
            my[c] = ml;
        }

        #pragma unroll
        for (int c = 0; c < 4; ++c) sY[cidx + c] = my[c];
    }

    // publish xmin partials
    #pragma unroll
    for (int k = 0; k < PTS; ++k) sPart[w][u + k * 32] = mn[k];
    __syncthreads();

    // combine xmin across warps -> exclusive transposed slot
    for (int q = tid; q < QPB; q += TPB) {
        float m = sPart[0][q];
        #pragma unroll
        for (int ww = 1; ww < NWARP; ++ww) m = fminf(m, sPart[ww][q]);
        g_xpart[b][qbase + q][blockIdx.z] = m;
    }
    // ymin -> exclusive transposed slot
    for (int i = tid; i < CPB; i += TPB)
        g_ypart[b][cbase + i][qb] = sY[i];
}

__global__ void pass2_kernel(float* out, float scale) {
    __shared__ float wsum[8];
    const int bx  = blockIdx.x;
    const int tid = threadIdx.x;
    float v = 0.0f;

    if (bx < P2_XBLK) {
        // x-side: 8 consecutive queries per thread -> 8 independent float4 loads
        const int t = bx * 256 + tid;          // 0 .. 4095
        const int base = t * 8;                // entry index into [B][N]
        const float4* p = reinterpret_cast<const float4*>(
            &g_xpart[base >> 12][base & 4095][0]);
        float4 r[8];
        #pragma unroll
        for (int k = 0; k < 8; ++k) r[k] = p[k];   // batched (MLP=8)
        #pragma unroll
        for (int k = 0; k < 8; ++k) {
            const float m = fminf(fminf(r[k].x, r[k].y), fminf(r[k].z, r[k].w));
            v += sqrtf(fmaxf(m, 0.0f) + EPS);
        }
    } else {
        // y-side: 4 candidates per thread -> 8 independent float4 loads
        const int t = (bx - P2_XBLK) * 256 + tid;   // 0 .. 8191
        const int base = t * 4;
        const float4* p = reinterpret_cast<const float4*>(
            &g_ypart[base >> 12][base & 4095][0]);
        float4 r[8];
        #pragma unroll
        for (int k = 0; k < 8; ++k) r[k] = p[k];   // batched (MLP=8)
        #pragma unroll
        for (int k = 0; k < 4; ++k) {
            const float m0 = fminf(fminf(r[2*k].x, r[2*k].y), fminf(r[2*k].z, r[2*k].w));
            const float m1 = fminf(fminf(r[2*k+1].x, r[2*k+1].y), fminf(r[2*k+1].z, r[2*k+1].w));
            v += sqrtf(fmaxf(fminf(m0, m1), 0.0f) + EPS);
        }
    }

    #pragma unroll
    for (int off = 16; off > 0; off >>= 1)
        v += __shfl_xor_sync(0xFFFFFFFFu, v, off);

    const int u = tid & 31;
    const int w = tid >> 5;
    if (u == 0) wsum[w] = v;
    __syncthreads();
    if (tid == 0) {
        float t = 0.0f;
        #pragma unroll
        for (int ww = 0; ww < 8; ++ww) t += wsum[ww];
        atomicAdd(out, t * scale);
    }
}

extern "C" void kernel_launch(void* const* d_in, const int* in_sizes, int n_in,
                              void* d_out, int out_size)
{
    const float* x1 = (const float*)d_in[0];
    const float* y1 = (const float*)d_in[1];
    float* out = (float*)d_out;

    dim3 grid(NQB, B_DIM, CSPLIT);   // (8, 8, 4) = 256 blocks x 8 warps
    chamfer_main<<<grid, TPB>>>(x1, y1, out);

    const float scale = 1.0f / (float)(B_DIM * N_PTS);
    pass2_kernel<<<P2_BLK, 256>>>(out, scale);
}